// round 15
// baseline (speedup 1.0000x reference)
#include <cuda_runtime.h>
#include <cstdint>

// XingLoss on GB300 (sm_103a). R15: paired-segment float4 loads.
// Fixed geometry: x_list (P=16384, N=1024, 2) float32, scale scalar.
// segn = N/4 = 256 segments per row; segment i uses points 3i..3i+3.
//
// Each thread handles 2 adjacent segments: floats [12u, 12u+14) of a row.
// 3 x LDG.128 cover [12u, 12u+12) with zero request redundancy; the 2
// boundary floats come from lane+1's first float4 via shuffle (lane 31
// does one predicated LDG.64). Tail identical to the proven R8 design.
#define N_POINTS        1024
#define ROW_FLOATS      (N_POINTS * 2)   // 2048
#define SEGN            256
#define ROWS_PER_BLOCK  8
#define NSLOTS          32

__device__ float        g_slots[NSLOTS];   // zero-init at load; reset each launch
__device__ unsigned int g_counter = 0;

// Crossing term for one segment given its 4 points.
__device__ __forceinline__ float seg_term(float2 p0, float2 p1, float2 p2, float2 p3)
{
    const float v1x = p1.x - p0.x, v1y = p1.y - p0.y;
    const float v2x = p2.x - p1.x, v2y = p2.y - p1.y;
    const float v3x = p3.x - p2.x, v3y = p3.y - p2.y;

    // direct = (s12 >= 0) depends only on sign of cross(v1,v2):
    // the positive norm product cannot flip the sign.
    const float c12 = v1x * v2y - v1y * v2x;
    const float c13 = v1x * v3y - v1y * v3x;

    const float n2   = (v1x * v1x + v1y * v1y) * (v3x * v3x + v3y * v3y);
    const float sina = c13 * rsqrtf(n2);

    return (c12 >= 0.0f) ? fmaxf(-sina, 0.0f) : fmaxf(sina, 0.0f);
}

__global__ void __launch_bounds__(SEGN, 8) xing_kernel(
    const float* __restrict__ x,
    const uint32_t* __restrict__ scale_raw,
    float* __restrict__ out, int P, int nblocks)
{
    const int t    = threadIdx.x;        // 0..255
    const int lane = t & 31;
    const int half = t >> 7;             // 0/1: which row of each row pair
    const int u    = t & 127;            // segment-pair index 0..127

    // This thread's pair starts at float 12u of its row (48u bytes, 16B-aligned).
    const float* __restrict__ blockbase =
        x + (size_t)blockIdx.x * ROWS_PER_BLOCK * ROW_FLOATS + 12 * u;

    float acc = 0.0f;

    #pragma unroll
    for (int r = 0; r < ROWS_PER_BLOCK / 2; r++) {
        const int    row = 2 * r + half;
        const float* rp  = blockbase + (size_t)row * ROW_FLOATS;
        const float4* q  = reinterpret_cast<const float4*>(rp);

        const float4 q0 = __ldg(q + 0);  // floats 12u+0 .. 12u+3
        const float4 q1 = __ldg(q + 1);  // floats 12u+4 .. 12u+7
        const float4 q2 = __ldg(q + 2);  // floats 12u+8 .. 12u+11

        // Boundary point (floats 12u+12, 12u+13) = next lane's q0.xy.
        float2 bnd = make_float2(0.0f, 0.0f);
        if (lane == 31)
            bnd = __ldg(reinterpret_cast<const float2*>(rp + 12));
        float bx = __shfl_down_sync(0xFFFFFFFFu, q0.x, 1);
        float by = __shfl_down_sync(0xFFFFFFFFu, q0.y, 1);
        if (lane == 31) { bx = bnd.x; by = bnd.y; }

        // Segment 2u:   points (f0,f1) (f2,f3) (f4,f5) (f6,f7)
        acc += seg_term(make_float2(q0.x, q0.y), make_float2(q0.z, q0.w),
                        make_float2(q1.x, q1.y), make_float2(q1.z, q1.w));
        // Segment 2u+1: points (f6,f7) (f8,f9) (f10,f11) (f12,f13)
        acc += seg_term(make_float2(q1.z, q1.w), make_float2(q2.x, q2.y),
                        make_float2(q2.z, q2.w), make_float2(bx, by));
    }

    // ---- block reduce ----
    #pragma unroll
    for (int o = 16; o > 0; o >>= 1)
        acc += __shfl_down_sync(0xFFFFFFFFu, acc, o);

    __shared__ float s[SEGN / 32];
    if (lane == 0) s[t >> 5] = acc;
    __syncthreads();

    // Thread 0 only: accumulate into spread slots, detect last block, finalize.
    if (t == 0) {
        float bs = 0.0f;
        #pragma unroll
        for (int i = 0; i < SEGN / 32; i++) bs += s[i];

        // 32 distinct L2 addresses, ~64 adds each, spread over the kernel
        // lifetime -> negligible atomic contention.
        atomicAdd(&g_slots[blockIdx.x & (NSLOTS - 1)], bs);
        __threadfence();
        unsigned int done = atomicAdd(&g_counter, 1u);

        if (done == (unsigned int)(nblocks - 1)) {
            float v[NSLOTS];
            #pragma unroll
            for (int i = 0; i < NSLOTS; i++) v[i] = __ldcg(&g_slots[i]);

            float total = 0.0f;
            #pragma unroll
            for (int i = 0; i < NSLOTS; i++) {
                total += v[i];
                g_slots[i] = 0.0f;
            }

            // Decode scale: float32 bit pattern vs integer bit pattern.
            uint32_t u32 = scale_raw[0];
            float    f   = __uint_as_float(u32);
            float    scale;
            if (fabsf(f) >= 1e-30f && fabsf(f) < 1e30f) scale = f;
            else                                        scale = (float)(int)u32;

            out[0] = total * scale / ((float)SEGN * (float)P);
            atomicExch(&g_counter, 0u);       // reset for next replay
        }
    }
}

extern "C" void kernel_launch(void* const* d_in, const int* in_sizes, int n_in,
                              void* d_out, int out_size)
{
    const float*    x     = (const float*)d_in[0];
    const uint32_t* scale = (const uint32_t*)d_in[1];
    float*          out   = (float*)d_out;

    int P       = in_sizes[0] / ROW_FLOATS;         // 16384
    int nblocks = P / ROWS_PER_BLOCK;               // 2048

    xing_kernel<<<nblocks, SEGN>>>(x, scale, out, P, nblocks);
}